// round 14
// baseline (speedup 1.0000x reference)
#include <cuda_runtime.h>
#include <cuda_bf16.h>

// ---------------- problem constants (1,3,224,224) ----------------
#define HH    224
#define WW    224
#define NPIX  (HH * WW)
#define WSR   10
#define KK    21            // 2*WSR+1

#define EPSF  1e-6f
#define EPS08 1.5848931924611134e-05f     // (1e-6)^0.8
#define C_LW  (-72.134752044448169f)      // -SIG_COLOR * log2(e)
#define SIG_SPACE_F (1.0f / 98.0f)        // 1/(7*7*2)
#define LOG2E 1.4426950408889634f
#define C1F   10.0f
#define C2F   5.0f

// ---------------- tiling ----------------
#define TX    32
#define TY    4
#define NZ    2
#define NTHR  (TX * TY * NZ)     // 256
#define RR    (TY + WSR)         // 14 halo rows (forward offsets: dy in [0,10])
#define CC    (TX + 2 * WSR)     // 52 halo cols
#define RC    (RR * CC)          // 728
#define GXB   (WW / TX)          // 7
#define GYB   (HH / TY)          // 56
#define NBLK  (GXB * GYB)        // 392

// ---------------- scratch (device globals: no allocation) ----------------
__device__ float    g_mask[NPIX];     // +1 = use_large, -1 = small branch
__device__ float    g_part[NBLK];     // per-block partial sums
__device__ unsigned g_counter = 0;    // last-block detector (reset each call)

// MUFU wrappers
__device__ __forceinline__ float ex2f(float x) {
    float y; asm("ex2.approx.f32 %0, %1;" : "=f"(y) : "f"(x)); return y;
}
__device__ __forceinline__ float lg2f(float x) {
    float y; asm("lg2.approx.f32 %0, %1;" : "=f"(y) : "f"(x)); return y;
}
// wr * t^0.8 fused: exp2(0.8*log2(t) + lw), lw = C_LW * cd
__device__ __forceinline__ float powterm(float t, float lw) {
    return ex2f(fmaf(0.8f, lg2f(t), lw));
}

// ============================================================================
// Pass 1: per-pixel branch mask (unchanged — fast).
// ============================================================================
__global__ __launch_bounds__(128) void mask_kernel(
    const float* __restrict__ orig, const float* __restrict__ smv)
{
    const int p = blockIdx.x * 128 + threadIdx.x;    // NPIX == 392*128 exactly
    const int y = p / WW, x = p - y * WW;

    const float oc0 = orig[p], oc1 = orig[NPIX + p], oc2 = orig[2 * NPIX + p];
    const bool xin = (x >= WSR) && (x < WW - WSR);

    float ero = 0.0f;
    #pragma unroll 1
    for (int dy = -WSR; dy <= WSR; ++dy) {
        int yy = y + dy;
        if ((unsigned)yy >= (unsigned)HH) continue;
        const float* r = orig + yy * WW;
        float rs = 0.0f;
        if (xin) {
            #pragma unroll
            for (int dx = -WSR; dx <= WSR; ++dx) {
                int q = x + dx;
                float o0 = r[q], o1 = r[NPIX + q], o2 = r[2 * NPIX + q];
                rs += (o0 > 0.0f) ? fabsf(o0 - oc0) : 0.0f;
                rs += (o1 > 0.0f) ? fabsf(o1 - oc1) : 0.0f;
                rs += (o2 > 0.0f) ? fabsf(o2 - oc2) : 0.0f;
            }
        } else {
            #pragma unroll
            for (int dx = -WSR; dx <= WSR; ++dx) {
                int xx = x + dx;
                bool v = (unsigned)xx < (unsigned)WW;
                int q = v ? xx : x;
                float o0 = r[q], o1 = r[NPIX + q], o2 = r[2 * NPIX + q];
                rs += (v && o0 > 0.0f) ? fabsf(o0 - oc0) : 0.0f;
                rs += (v && o1 > 0.0f) ? fabsf(o1 - oc1) : 0.0f;
                rs += (v && o2 > 0.0f) ? fabsf(o2 - oc2) : 0.0f;
            }
        }
        ero += rs;
        if (ero >= C1F) break;   // terms non-negative: final er_o >= partial
    }

    bool useL = false;
    if (ero < C1F) {
        float sc0 = smv[p], sc1 = smv[NPIX + p], sc2 = smv[2 * NPIX + p];
        float ers = 0.0f;
        int xlo = max(x - WSR, 0), xhi = min(x + WSR, WW - 1);
        int ylo = max(y - WSR, 0), yhi = min(y + WSR, HH - 1);
        for (int yy = ylo; yy <= yhi; ++yy) {
            int rowb = yy * WW;
            for (int xx = xlo; xx <= xhi; ++xx) {
                int q = rowb + xx;
                float s0 = smv[q], s1 = smv[NPIX + q], s2 = smv[2 * NPIX + q];
                ers += (s0 > 0.0f) ? fabsf(s0 - sc0) : 0.0f;
                ers += (s1 > 0.0f) ? fabsf(s1 - sc1) : 0.0f;
                ers += (s2 > 0.0f) ? fabsf(s2 - sc2) : 0.0f;
            }
        }
        useL = (ers - ero) > C2F;
    }
    g_mask[p] = useL ? 1.0f : -1.0f;
}

// ============================================================================
// Pass 2 variants. Forward-offset sets per z-half (both 110 pairs):
//   z=0: {dy=0, dx=1..10} U {dy=1..10, dx=-10..-1}
//   z=1: {dy=1..10, dx=0..10}
// ============================================================================
__device__ __forceinline__ float ptsum_pair(
    const float* __restrict__ ssp, const float* __restrict__ osp, int off,
    float si0, float si1, float si2, float oi0, float oi1, float oi2)
{
    float sj0 = ssp[off], sj1 = ssp[RC + off], sj2 = ssp[2 * RC + off];
    float oj0 = osp[off], oj1 = osp[RC + off], oj2 = osp[2 * RC + off];
    float d0 = oj0 - oi0, d1 = oj1 - oi1, d2 = oj2 - oi2;
    float lw = fmaf(d0, d0, fmaf(d1, d1, d2 * d2)) * C_LW;   // log2(wr)
    float t0 = fabsf(sj0 - si0) + EPSF;
    float t1 = fabsf(sj1 - si1) + EPSF;
    float t2 = fabsf(sj2 - si2) + EPSF;
    return powterm(t0, lw) + powterm(t1, lw) + powterm(t2, lw);
}

// FAST: no use_large anywhere, all in-bounds s>0. EDGEV: forward/side halo may
// be OOB (zeroed, v=0); pair weight w = -2*v_j in {2,0}. Full-window OOB count
// handled analytically (z=0 thread only).
template <bool EDGEV, int Z>
__device__ __forceinline__ float window_fast(
    const float* __restrict__ ssp, const float* __restrict__ osp,
    const float* __restrict__ vsp, int base, int gx, int gy)
{
    const float si0 = ssp[base], si1 = ssp[RC + base], si2 = ssp[2 * RC + base];
    const float oi0 = osp[base], oi1 = osp[RC + base], oi2 = osp[2 * RC + base];

    float acc = 0.0f;
    if (Z == 0) {
        // self term + analytic FULL-window OOB terms (wSi == 1)
        int ninx = min(gx, WSR) + min(WW - 1 - gx, WSR) + 1;
        int niny = min(gy, WSR) + min(HH - 1 - gy, WSR) + 1;
        float noob = (float)(KK * KK - ninx * niny);
        float cdo  = fmaf(oi0, oi0, fmaf(oi1, oi1, oi2 * oi2));
        acc = (3.0f * EPS08) * fmaf(noob, ex2f(C_LW * cdo), 1.0f);
    }

    auto pair = [&](int off) {
        float p = ptsum_pair(ssp, osp, off, si0, si1, si2, oi0, oi1, oi2);
        if (EDGEV) acc = fmaf(-2.0f * vsp[off], p, acc);
        else       acc = fmaf(2.0f, p, acc);
    };

    if (Z == 0) {
        #pragma unroll
        for (int dx = 1; dx <= WSR; ++dx) pair(base + dx);
        #pragma unroll 1
        for (int dy = 1; dy <= WSR; ++dy) {
            int rb = base + dy * CC;
            #pragma unroll
            for (int dx = -WSR; dx <= -1; ++dx) pair(rb + dx);
        }
    } else {
        #pragma unroll 1
        for (int dy = 1; dy <= WSR; ++dy) {
            int rb = base + dy * CC;
            #pragma unroll
            for (int dx = 0; dx <= WSR; ++dx) pair(rb + dx);
        }
    }
    return acc;
}

// SAFE: R12-proven branch-free select body (handles exact-zero samples and
// use_large pixels). Backward-OOB analytic; forward-OOB via halo zeros.
template <bool LARGE, int Z>
__device__ __forceinline__ float window_safe(
    const float* __restrict__ ssp, const float* __restrict__ osp,
    const float* __restrict__ vsp, const float* __restrict__ ws1d,
    int base, int gx, int gy)
{
    const float si0 = ssp[base], si1 = ssp[RC + base], si2 = ssp[2 * RC + base];
    const float oi0 = osp[base], oi1 = osp[RC + base], oi2 = osp[2 * RC + base];
    float wLi = 0.0f, wSi = 1.0f;
    if (LARGE) {
        float vi = vsp[base];
        wLi = fmaxf(vi, 0.0f); wSi = fmaxf(-vi, 0.0f);
    }
    const bool pi0 = (si0 > 0.0f), pi1 = (si1 > 0.0f), pi2 = (si2 > 0.0f);

    float acc = 0.0f;
    if (Z == 0) {
        // self term + analytic BACKWARD-OOB terms
        int left  = max(WSR - gx, 0);
        int right = max(gx - (WW - 1 - WSR), 0);
        int up    = max(WSR - gy, 0);
        int inRowsBack = min(gy, WSR);
        float noob = (float)(left * (1 + inRowsBack) + KK * up + right * inRowsBack);
        float cdo  = fmaf(oi0, oi0, fmaf(oi1, oi1, oi2 * oi2));
        acc = wSi * (3.0f * EPS08) * fmaf(noob, ex2f(C_LW * cdo), 1.0f);
    }

    auto pair = [&](int off, float aw) {
        float sj0 = ssp[off], sj1 = ssp[RC + off], sj2 = ssp[2 * RC + off];
        float oj0 = osp[off], oj1 = osp[RC + off], oj2 = osp[2 * RC + off];
        float vj  = vsp[off];
        float d0 = oj0 - oi0, d1 = oj1 - oi1, d2 = oj2 - oi2;
        float lw = fmaf(d0, d0, fmaf(d1, d1, d2 * d2)) * C_LW;
        float e0 = sj0 - si0, e1 = sj1 - si1, e2 = sj2 - si2;
        float pt0 = powterm(fabsf(e0) + EPSF, lw);
        float pt1 = powterm(fabsf(e1) + EPSF, lw);
        float pt2 = powterm(fabsf(e2) + EPSF, lw);
        float ew  = EPS08 * ex2f(lw);                  // wr * eps^0.8
        bool  pj0 = (sj0 > 0.0f), pj1 = (sj1 > 0.0f), pj2 = (sj2 > 0.0f);
        float pA = (pj0 ? pt0 : ew) + (pj1 ? pt1 : ew) + (pj2 ? pt2 : ew);
        float pB = (pi0 ? pt0 : ew) + (pi1 ? pt1 : ew) + (pi2 ? pt2 : ew);
        float wSj = fmaxf(-vj, 0.0f);
        if (LARGE) {
            acc = fmaf(wSi, pA, fmaf(wSj, pB, acc));
            float q0 = e0 * e0, q1 = e1 * e1, q2 = e2 * e2;
            float QA = (pj0 ? q0 : 0.0f) + (pj1 ? q1 : 0.0f) + (pj2 ? q2 : 0.0f);
            float QB = (pi0 ? q0 : 0.0f) + (pi1 ? q1 : 0.0f) + (pi2 ? q2 : 0.0f);
            float wLj = fmaxf(vj, 0.0f);
            acc = fmaf(aw, fmaf(wLi, QA, wLj * QB), acc);
        } else {
            acc = fmaf(wSj, pB, acc + pA);   // wSi == 1 in all-small tile
        }
    };

    if (Z == 0) {
        float ay0 = LARGE ? 5.0f * ws1d[WSR] : 0.0f;
        #pragma unroll
        for (int dx = 1; dx <= WSR; ++dx)
            pair(base + dx, LARGE ? ay0 * ws1d[WSR + dx] : 0.0f);
        #pragma unroll 1
        for (int dy = 1; dy <= WSR; ++dy) {
            float ayw = LARGE ? 5.0f * ws1d[WSR + dy] : 0.0f;
            int rb = base + dy * CC;
            #pragma unroll
            for (int dx = -WSR; dx <= -1; ++dx)
                pair(rb + dx, LARGE ? ayw * ws1d[WSR + dx] : 0.0f);
        }
    } else {
        #pragma unroll 1
        for (int dy = 1; dy <= WSR; ++dy) {
            float ayw = LARGE ? 5.0f * ws1d[WSR + dy] : 0.0f;
            int rb = base + dy * CC;
            #pragma unroll
            for (int dx = 0; dx <= WSR; ++dx)
                pair(rb + dx, LARGE ? ayw * ws1d[WSR + dx] : 0.0f);
        }
    }
    return acc;
}

__global__ __launch_bounds__(NTHR) void loss_kernel(
    const float* __restrict__ orig, const float* __restrict__ smv,
    float* __restrict__ out)
{
    __shared__ float  ssm[3 * RC];
    __shared__ float  som[3 * RC];
    __shared__ float  svm[RC];
    __shared__ float  ws1d[KK];
    __shared__ int    s_hasL, s_hasZ, s_last;
    __shared__ float  red[NTHR];
    __shared__ double rd[NTHR];

    const int tid = (threadIdx.z * TY + threadIdx.y) * TX + threadIdx.x;
    if (tid == 0) { s_hasL = 0; s_hasZ = 0; s_last = 0; }
    if (tid < KK) {
        int d = tid - WSR;
        ws1d[tid] = ex2f(-SIG_SPACE_F * LOG2E * (float)(d * d));
    }

    const int x0 = blockIdx.x * TX, y0 = blockIdx.y * TY;

    int fL = 0, fZ = 0;
    for (int idx = tid; idx < RC; idx += NTHR) {
        int r = idx / CC, i = idx - r * CC;
        int gy = y0 + r, gx = x0 - WSR + i;
        float s0 = 0, s1 = 0, s2 = 0, o0 = 0, o1 = 0, o2 = 0, v = 0;
        if (gy < HH && (unsigned)gx < (unsigned)WW) {
            int gi = gy * WW + gx;
            s0 = smv[gi]; s1 = smv[NPIX + gi]; s2 = smv[2 * NPIX + gi];
            o0 = orig[gi]; o1 = orig[NPIX + gi]; o2 = orig[2 * NPIX + gi];
            v  = g_mask[gi];
            fZ |= (fminf(s0, fminf(s1, s2)) <= 0.0f) ? 1 : 0;  // in-bounds zeros only
        }
        ssm[idx] = s0; ssm[RC + idx] = s1; ssm[2 * RC + idx] = s2;
        som[idx] = o0; som[RC + idx] = o1; som[2 * RC + idx] = o2;
        svm[idx] = v;
        fL |= (v > 0.0f) ? 1 : 0;
    }
    if (fL) s_hasL = 1;
    if (fZ) s_hasZ = 1;
    __syncthreads();

    const bool hasOOB = (blockIdx.x == 0) | (blockIdx.x == GXB - 1) | (y0 + RR > HH);
    const int gx = x0 + threadIdx.x, gy = y0 + threadIdx.y;
    const int base = threadIdx.y * CC + threadIdx.x + WSR;

    float acc;
    if (threadIdx.z == 0) {
        if (s_hasL)      acc = window_safe<true , 0>(ssm, som, svm, ws1d, base, gx, gy);
        else if (s_hasZ) acc = window_safe<false, 0>(ssm, som, svm, ws1d, base, gx, gy);
        else if (hasOOB) acc = window_fast<true , 0>(ssm, som, svm, base, gx, gy);
        else             acc = window_fast<false, 0>(ssm, som, svm, base, gx, gy);
    } else {
        if (s_hasL)      acc = window_safe<true , 1>(ssm, som, svm, ws1d, base, gx, gy);
        else if (s_hasZ) acc = window_safe<false, 1>(ssm, som, svm, ws1d, base, gx, gy);
        else if (hasOOB) acc = window_fast<true , 1>(ssm, som, svm, base, gx, gy);
        else             acc = window_fast<false, 1>(ssm, som, svm, base, gx, gy);
    }

    red[tid] = acc;
    __syncthreads();
    #pragma unroll
    for (int s = NTHR / 2; s > 0; s >>= 1) {
        if (tid < s) red[tid] += red[tid + s];
        __syncthreads();
    }

    const int bid = blockIdx.y * gridDim.x + blockIdx.x;
    if (tid == 0) {
        g_part[bid] = red[0];
        __threadfence();
        unsigned old = atomicAdd(&g_counter, 1u);
        s_last = (old == (unsigned)(NBLK - 1)) ? 1 : 0;
    }
    __syncthreads();

    // Last block: deterministic fp64 finalize (fixed index order).
    if (s_last) {
        double s = 0.0;
        for (int i = tid; i < NBLK; i += NTHR) s += (double)__ldcg(&g_part[i]);
        rd[tid] = s;
        __syncthreads();
        #pragma unroll
        for (int k = NTHR / 2; k > 0; k >>= 1) {
            if (tid < k) rd[tid] += rd[tid + k];
            __syncthreads();
        }
        if (tid == 0) {
            const double scale = 1.0 / ((double)HH * (double)WW) / (double)(WSR * WSR);
            out[0] = (float)(rd[0] * scale);
            g_counter = 0;   // reset for next graph replay
        }
    }
}

extern "C" void kernel_launch(void* const* d_in, const int* in_sizes, int n_in,
                              void* d_out, int out_size)
{
    (void)in_sizes; (void)n_in; (void)out_size;
    const float* orig = (const float*)d_in[0];   // original_images (1,3,224,224)
    const float* smv  = (const float*)d_in[1];   // smooth_images   (1,3,224,224)
    float* out = (float*)d_out;

    mask_kernel<<<NPIX / 128, 128>>>(orig, smv);

    dim3 grid(GXB, GYB);
    dim3 blk(TX, TY, NZ);
    loss_kernel<<<grid, blk>>>(orig, smv, out);
}